// round 1
// baseline (speedup 1.0000x reference)
#include <cuda_runtime.h>
#include <cuda_bf16.h>
#include <math.h>

// Problem constants
#define BATCH 2
#define SEQ   4096
#define HID   2048
#define DK    128
#define CHUNK 64
#define NCHUNK 64                  // per batch
#define NCC   (BATCH*NCHUNK)       // 128 total batch-chunks
#define NTOK  (BATCH*SEQ)          // 8192

// ---------------- scratch (device globals; no cudaMalloc allowed) -------------
__device__ float g_sq[(size_t)NTOK*DK];         // q scores -> q (softmax)
__device__ float g_sk[(size_t)NTOK*DK];         // k scores -> k (sigmoid)
__device__ float g_QE[(size_t)NCC*CHUNK*DK];    // q * exp(B - Bm)
__device__ float g_KE[(size_t)NCC*CHUNK*DK];    // k * exp(Bm - B)
__device__ float g_qb[(size_t)NCC*CHUNK*DK];    // q * exp(B)
__device__ float g_kd[(size_t)NCC*CHUNK*DK];    // k * exp(Blast - B)
__device__ float g_el[NCC*DK];                  // exp(Blast)
__device__ float g_A [(size_t)NCC*CHUNK*CHUNK]; // tril intra matrices
__device__ float g_T [(size_t)NCC*DK*HID];      // T_c then (in-place) S_before_c  (128MB)
__device__ float g_o [(size_t)NTOK*HID];        // attention output o
__device__ float g_G [(size_t)NTOK*HID];        // gate scores -> gated/normed t

// ---------------- f32x2 helpers ----------------------------------------------
__device__ __forceinline__ void fma2(unsigned long long& d, unsigned long long a,
                                     unsigned long long b) {
    asm("fma.rn.f32x2 %0, %1, %2, %0;" : "+l"(d) : "l"(a), "l"(b));
}
__device__ __forceinline__ float2 u2f2(unsigned long long v) {
    float2 r; asm("mov.b64 {%0,%1}, %2;" : "=f"(r.x), "=f"(r.y) : "l"(v)); return r;
}

// ---------------- generic GEMM: C[M,N] (+)= A[M,K] * B[N,K]^T -----------------
// Both operands K-contiguous (all our GEMMs are X @ W^T). f32x2 packed along K.
#define GBM 128
#define GBN 64
#define GBK 32
#define GLD (GBK+4)   // 36-float row stride: 16B aligned, conflict-free micro map

__global__ __launch_bounds__(256, 1) void sgemm_tn(
    const float* __restrict__ A, const float* __restrict__ B, float* __restrict__ C,
    int M, int N, int K, int accum)
{
    __shared__ __align__(16) float As[GBM][GLD];
    __shared__ __align__(16) float Bs[GBN][GLD];
    const int tid = threadIdx.x;
    const int tx = tid & 15, ty = tid >> 4;
    const long bm = (long)blockIdx.y * GBM;
    const long bn = (long)blockIdx.x * GBN;

    unsigned long long acc[8][4];
#pragma unroll
    for (int i = 0; i < 8; i++)
#pragma unroll
        for (int j = 0; j < 4; j++) acc[i][j] = 0ull;

    for (int k0 = 0; k0 < K; k0 += GBK) {
#pragma unroll
        for (int r = 0; r < 4; r++) {               // A tile 128x32
            int idx = tid + 256 * r;
            int row = idx >> 3, seg = idx & 7;
            *(float4*)&As[row][seg * 4] =
                *(const float4*)(A + (bm + row) * (long)K + k0 + seg * 4);
        }
#pragma unroll
        for (int r = 0; r < 2; r++) {               // B tile 64x32
            int idx = tid + 256 * r;
            int row = idx >> 3, seg = idx & 7;
            *(float4*)&Bs[row][seg * 4] =
                *(const float4*)(B + (bn + row) * (long)K + k0 + seg * 4);
        }
        __syncthreads();
#pragma unroll
        for (int kk = 0; kk < GBK; kk += 4) {
            ulonglong2 av[8]; ulonglong2 bv[4];
#pragma unroll
            for (int i = 0; i < 8; i++) av[i] = *(const ulonglong2*)&As[ty + i * 16][kk];
#pragma unroll
            for (int j = 0; j < 4; j++) bv[j] = *(const ulonglong2*)&Bs[tx + j * 16][kk];
#pragma unroll
            for (int i = 0; i < 8; i++)
#pragma unroll
                for (int j = 0; j < 4; j++) fma2(acc[i][j], av[i].x, bv[j].x);
#pragma unroll
            for (int i = 0; i < 8; i++)
#pragma unroll
                for (int j = 0; j < 4; j++) fma2(acc[i][j], av[i].y, bv[j].y);
        }
        __syncthreads();
    }
#pragma unroll
    for (int i = 0; i < 8; i++) {
        long m = bm + ty + i * 16;
#pragma unroll
        for (int j = 0; j < 4; j++) {
            long n = bn + tx + j * 16;
            float2 p = u2f2(acc[i][j]);
            float s = p.x + p.y;
            if (accum) C[m * (long)N + n] += s;
            else       C[m * (long)N + n] = s;
        }
    }
}

// ---------------- q softmax / k sigmoid (in-place on score buffers) -----------
__global__ void qk_act(float* __restrict__ sq, float* __restrict__ sk)
{
    int t = blockIdx.x, d = threadIdx.x;            // 128 threads
    int lane = d & 31, w = d >> 5;
    __shared__ float sm[4], ss[4];
    size_t idx = (size_t)t * DK + d;
    float v = sq[idx];
    float m = v;
#pragma unroll
    for (int o = 16; o; o >>= 1) m = fmaxf(m, __shfl_xor_sync(0xffffffffu, m, o));
    if (!lane) sm[w] = m;
    __syncthreads();
    m = fmaxf(fmaxf(sm[0], sm[1]), fmaxf(sm[2], sm[3]));
    float e = expf(v - m);
    float s = e;
#pragma unroll
    for (int o = 16; o; o >>= 1) s += __shfl_xor_sync(0xffffffffu, s, o);
    if (!lane) ss[w] = s;
    __syncthreads();
    s = ss[0] + ss[1] + ss[2] + ss[3];
    sq[idx] = e / s;
    float kv = sk[idx];
    sk[idx] = 1.f / (1.f + expf(-kv));
}

// ---------------- per-chunk decay prep ----------------------------------------
// gf = log_sigmoid(-k) = -log1p(exp(k)); B = cumsum(gf) (inclusive).
__global__ void chunk_prep(const float* __restrict__ q, const float* __restrict__ k)
{
    int cc = blockIdx.x;                 // batch-chunk
    int d = threadIdx.x;                 // 128 threads, one per dk
    size_t base = (size_t)cc * CHUNK * DK + d;
    float Bl = 0.f;
    for (int i = 0; i < CHUNK; i++) {
        float kv = k[base + (size_t)i * DK];
        Bl -= log1pf(expf(kv));
    }
    float Bm = 0.5f * Bl;
    float B = 0.f;
    for (int i = 0; i < CHUNK; i++) {
        size_t idx = base + (size_t)i * DK;
        float kv = k[idx];
        float qv = q[idx];
        B -= log1pf(expf(kv));
        g_QE[idx] = qv * expf(B - Bm);
        g_KE[idx] = kv * expf(Bm - B);
        g_qb[idx] = qv * expf(B);
        g_kd[idx] = kv * expf(Bl - B);
    }
    g_el[cc * DK + d] = expf(Bl);
}

// ---------------- A = tril(QE @ KE^T) per chunk (64x64, K=128) ----------------
__global__ __launch_bounds__(256) void a_gemm()
{
    int cc = blockIdx.x;
    int tid = threadIdx.x, tx = tid & 15, ty = tid >> 4;
    __shared__ float Qs[64][33];
    __shared__ float Ks[64][33];
    float acc[4][4] = {};
    const float* Q  = g_QE + (size_t)cc * CHUNK * DK;
    const float* Kp = g_KE + (size_t)cc * CHUNK * DK;
    for (int k0 = 0; k0 < DK; k0 += 32) {
#pragma unroll
        for (int r = 0; r < 8; r++) {
            int idx = tid + 256 * r;
            int row = idx >> 5, kk = idx & 31;
            Qs[row][kk] = Q [row * DK + k0 + kk];
            Ks[row][kk] = Kp[row * DK + k0 + kk];
        }
        __syncthreads();
#pragma unroll
        for (int kk = 0; kk < 32; kk++) {
            float a[4], b[4];
#pragma unroll
            for (int i = 0; i < 4; i++) a[i] = Qs[ty * 4 + i][kk];
#pragma unroll
            for (int j = 0; j < 4; j++) b[j] = Ks[tx * 4 + j][kk];
#pragma unroll
            for (int i = 0; i < 4; i++)
#pragma unroll
                for (int j = 0; j < 4; j++) acc[i][j] = fmaf(a[i], b[j], acc[i][j]);
        }
        __syncthreads();
    }
#pragma unroll
    for (int i = 0; i < 4; i++)
#pragma unroll
        for (int j = 0; j < 4; j++) {
            int I = ty * 4 + i, J = tx * 4 + j;
            g_A[(size_t)cc * CHUNK * CHUNK + I * CHUNK + J] = (J <= I) ? acc[i][j] : 0.f;
        }
}

// ---------------- T_c[d,v] = sum_i kd[i,d] * v[i,v]   (128x2048, K=64) --------
__global__ __launch_bounds__(256) void t_gemm(const float* __restrict__ x)
{
    int cc = blockIdx.y;
    int vb = blockIdx.x * 64;
    int tid = threadIdx.x, tx = tid & 15, ty = tid >> 4;
    __shared__ __align__(16) float kds[32][132];   // [i(k)][d]
    __shared__ __align__(16) float xs[32][68];     // [i(k)][v]
    float acc[8][4] = {};
    const float* kd = g_kd + (size_t)cc * CHUNK * DK;

    for (int k0 = 0; k0 < CHUNK; k0 += 32) {
#pragma unroll
        for (int r = 0; r < 4; r++) {              // kd tile 32x128
            int idx = tid + 256 * r;
            int row = idx >> 5, seg = idx & 31;
            *(float4*)&kds[row][seg * 4] =
                *(const float4*)(kd + (size_t)(k0 + row) * DK + seg * 4);
        }
#pragma unroll
        for (int r = 0; r < 2; r++) {              // v tile 32x64
            int idx = tid + 256 * r;
            int row = idx >> 4, seg = idx & 15;
            *(float4*)&xs[row][seg * 4] =
                *(const float4*)(x + (size_t)(cc * CHUNK + k0 + row) * HID + vb + seg * 4);
        }
        __syncthreads();
#pragma unroll
        for (int kk = 0; kk < 32; kk++) {
            float a[8], b[4];
            *(float4*)&a[0] = *(float4*)&kds[kk][ty * 8];
            *(float4*)&a[4] = *(float4*)&kds[kk][ty * 8 + 4];
            *(float4*)&b[0] = *(float4*)&xs[kk][tx * 4];
#pragma unroll
            for (int i = 0; i < 8; i++)
#pragma unroll
                for (int j = 0; j < 4; j++) acc[i][j] = fmaf(a[i], b[j], acc[i][j]);
        }
        __syncthreads();
    }
    float* T = g_T + (size_t)cc * DK * HID;
#pragma unroll
    for (int i = 0; i < 8; i++) {
        float4 o4 = make_float4(acc[i][0], acc[i][1], acc[i][2], acc[i][3]);
        *(float4*)(T + (size_t)(ty * 8 + i) * HID + vb + tx * 4) = o4;
    }
}

// ---------------- chunk-state scan: in-place T -> S_before --------------------
__global__ void scan_k()
{
    int gid = blockIdx.x * blockDim.x + threadIdx.x;   // 131072 threads
    int vg = gid & 511;
    int rest = gid >> 9;
    int d = rest & 127;
    int b = rest >> 7;
    float4 s = make_float4(0.f, 0.f, 0.f, 0.f);
    for (int c = 0; c < NCHUNK; c++) {
        int cc = b * NCHUNK + c;
        float e = g_el[cc * DK + d];
        float4* p = (float4*)&g_T[((size_t)cc * DK + d) * HID + vg * 4];
        float4 t = *p;
        *p = s;                                        // S before chunk c
        s.x = fmaf(s.x, e, t.x);
        s.y = fmaf(s.y, e, t.y);
        s.z = fmaf(s.z, e, t.z);
        s.w = fmaf(s.w, e, t.w);
    }
}

// ---------------- o = A @ v + qb @ S_before  (64x2048 per chunk) --------------
__global__ __launch_bounds__(256) void o_gemm(const float* __restrict__ x)
{
    int cc = blockIdx.y;
    int vb = blockIdx.x * 64;
    int tid = threadIdx.x, tx = tid & 15, ty = tid >> 4;
    __shared__ float Ls[64][33];
    __shared__ float Rs[32][65];
    float acc[4][4] = {};

    for (int ph = 0; ph < 2; ph++) {
        int KK = ph ? DK : CHUNK;
        const float* L = ph ? (g_qb + (size_t)cc * CHUNK * DK)
                            : (g_A + (size_t)cc * CHUNK * CHUNK);
        int lstride = ph ? DK : CHUNK;
        for (int k0 = 0; k0 < KK; k0 += 32) {
#pragma unroll
            for (int r = 0; r < 8; r++) {          // LHS tile 64x32
                int idx = tid + 256 * r;
                int row = idx >> 5, kk = idx & 31;
                Ls[row][kk] = L[(size_t)row * lstride + k0 + kk];
            }
#pragma unroll
            for (int r = 0; r < 8; r++) {          // RHS tile 32x64
                int idx = tid + 256 * r;
                int kk = idx >> 6, v = idx & 63;
                float val;
                if (ph == 0)
                    val = x[(size_t)(cc * CHUNK + k0 + kk) * HID + vb + v];
                else
                    val = g_T[(size_t)cc * DK * HID + (size_t)(k0 + kk) * HID + vb + v];
                Rs[kk][v] = val;
            }
            __syncthreads();
#pragma unroll
            for (int kk = 0; kk < 32; kk++) {
                float a[4], b[4];
#pragma unroll
                for (int i = 0; i < 4; i++) a[i] = Ls[ty * 4 + i][kk];
#pragma unroll
                for (int j = 0; j < 4; j++) b[j] = Rs[kk][tx * 4 + j];
#pragma unroll
                for (int i = 0; i < 4; i++)
#pragma unroll
                    for (int j = 0; j < 4; j++) acc[i][j] = fmaf(a[i], b[j], acc[i][j]);
            }
            __syncthreads();
        }
    }
#pragma unroll
    for (int i = 0; i < 4; i++)
#pragma unroll
        for (int j = 0; j < 4; j++)
            g_o[(size_t)(cc * CHUNK + ty * 4 + i) * HID + vb + tx * 4 + j] = acc[i][j];
}

// ---------------- rmsnorm(o)*gw * silu(G)  -> G (in place) --------------------
__global__ __launch_bounds__(256) void gate_norm(const float* __restrict__ o,
                                                 float* __restrict__ G,
                                                 const float* __restrict__ gw)
{
    int t = blockIdx.x, tid = threadIdx.x;
    int lane = tid & 31, w = tid >> 5;
    const float* orow = o + (size_t)t * HID;
    float* grow = G + (size_t)t * HID;
    float s = 0.f;
    for (int c = tid; c < HID; c += 256) { float v = orow[c]; s = fmaf(v, v, s); }
#pragma unroll
    for (int off = 16; off; off >>= 1) s += __shfl_xor_sync(0xffffffffu, s, off);
    __shared__ float red[8];
    if (!lane) red[w] = s;
    __syncthreads();
    float tot = 0.f;
#pragma unroll
    for (int i = 0; i < 8; i++) tot += red[i];
    float r = rsqrtf(tot * (1.0f / HID) + 1e-5f);
    for (int c = tid; c < HID; c += 256) {
        float on = orow[c] * r * gw[c];
        float g = grow[c];
        grow[c] = on * g / (1.f + expf(-g));
    }
}

// ---------------- launch ------------------------------------------------------
extern "C" void kernel_launch(void* const* d_in, const int* in_sizes, int n_in,
                              void* d_out, int out_size)
{
    const float* x   = (const float*)d_in[0];
    const float* Wq  = (const float*)d_in[1];
    const float* Wk  = (const float*)d_in[2];
    const float* Wog = (const float*)d_in[3];
    const float* Wig = (const float*)d_in[4];
    const float* Wo  = (const float*)d_in[5];
    const float* gw  = (const float*)d_in[6];
    float* out = (float*)d_out;

    float *sq, *sk, *o_, *G;
    cudaGetSymbolAddress((void**)&sq, g_sq);
    cudaGetSymbolAddress((void**)&sk, g_sk);
    cudaGetSymbolAddress((void**)&o_, g_o);
    cudaGetSymbolAddress((void**)&G,  g_G);

    // 1. q/k projections: scores = x @ W^T   (8192x128, K=2048)
    sgemm_tn<<<dim3(DK / GBN, NTOK / GBM), 256>>>(x, Wq, sq, NTOK, DK, HID, 0);
    sgemm_tn<<<dim3(DK / GBN, NTOK / GBM), 256>>>(x, Wk, sk, NTOK, DK, HID, 0);
    // 2. softmax / sigmoid
    qk_act<<<NTOK, DK>>>(sq, sk);
    // 3. per-chunk decay factors
    chunk_prep<<<NCC, DK>>>(sq, sk);
    // 4. intra-chunk matrices
    a_gemm<<<NCC, 256>>>();
    // 5. per-chunk state contributions T_c
    t_gemm<<<dim3(HID / 64, NCC), 256>>>(x);
    // 6. recurrent scan (in-place: T -> S_before)
    scan_k<<<512, 256>>>();
    // 7. o = A@v + qb@S_before
    o_gemm<<<dim3(HID / 64, NCC), 256>>>(x);
    // 8. gates: G = o@Wog^T + x@Wig^T
    sgemm_tn<<<dim3(HID / GBN, NTOK / GBM), 256>>>(o_, Wog, G, NTOK, HID, HID, 0);
    sgemm_tn<<<dim3(HID / GBN, NTOK / GBM), 256>>>(x,  Wig, G, NTOK, HID, HID, 1);
    // 9. rmsnorm + silu gating (in place on G)
    gate_norm<<<NTOK, 256>>>(o_, G, gw);
    // 10. final projection
    sgemm_tn<<<dim3(HID / GBN, NTOK / GBM), 256>>>(G, Wo, out, NTOK, HID, HID, 0);
}

// round 4
// speedup vs baseline: 2.7220x; 2.7220x over previous
#include <cuda_runtime.h>
#include <cuda_bf16.h>
#include <cstdint>
#include <math.h>

// Problem constants
#define BATCH 2
#define SEQ   4096
#define HID   2048
#define DK    128
#define CHUNK 64
#define NCHUNK 64                  // per batch
#define NCC   (BATCH*NCHUNK)       // 128 total batch-chunks
#define NTOK  (BATCH*SEQ)          // 8192

typedef __nv_bfloat16  bf16;
typedef __nv_bfloat162 bf162;

// ---------------- fp32 scratch ------------------------------------------------
__device__ float g_sq[(size_t)NTOK*DK];         // q scores -> q (softmax)
__device__ float g_sk[(size_t)NTOK*DK];         // k scores -> k (sigmoid)
__device__ float g_QE[(size_t)NCC*CHUNK*DK];    // q * exp(B - Bm)
__device__ float g_KE[(size_t)NCC*CHUNK*DK];    // k * exp(Bm - B)
__device__ float g_qb[(size_t)NCC*CHUNK*DK];    // q * exp(B)
__device__ float g_kd[(size_t)NCC*CHUNK*DK];    // k * exp(Blast - B)
__device__ float g_el[NCC*DK];                  // exp(Blast)
__device__ float g_A [(size_t)NCC*CHUNK*CHUNK]; // tril intra matrices
__device__ float g_T [(size_t)NCC*DK*HID];      // T_c then (in-place) S_before_c
__device__ float g_o [(size_t)NTOK*HID];        // attention output o (fp32)
__device__ float g_G [(size_t)NTOK*HID];        // gate scores

// ---------------- bf16 hi/lo scratch ------------------------------------------
__device__ __align__(16) bf16 g_xh [(size_t)NTOK*HID];
__device__ __align__(16) bf16 g_xl [(size_t)NTOK*HID];
__device__ __align__(16) bf16 g_wqh[(size_t)DK*HID];
__device__ __align__(16) bf16 g_wql[(size_t)DK*HID];
__device__ __align__(16) bf16 g_wkh[(size_t)DK*HID];
__device__ __align__(16) bf16 g_wkl[(size_t)DK*HID];
__device__ __align__(16) bf16 g_wogh[(size_t)HID*HID];
__device__ __align__(16) bf16 g_wogl[(size_t)HID*HID];
__device__ __align__(16) bf16 g_wigh[(size_t)HID*HID];
__device__ __align__(16) bf16 g_wigl[(size_t)HID*HID];
__device__ __align__(16) bf16 g_woh[(size_t)HID*HID];
__device__ __align__(16) bf16 g_wol[(size_t)HID*HID];
__device__ __align__(16) bf16 g_oh [(size_t)NTOK*HID];
__device__ __align__(16) bf16 g_ol [(size_t)NTOK*HID];
__device__ __align__(16) bf16 g_th [(size_t)NTOK*HID];
__device__ __align__(16) bf16 g_tl [(size_t)NTOK*HID];

// ---------------- helpers -----------------------------------------------------
__device__ __forceinline__ uint32_t smem_u32(const void* p) {
    uint32_t a;
    asm("{ .reg .u64 t; cvta.to.shared.u64 t, %1; cvt.u32.u64 %0, t; }" : "=r"(a) : "l"(p));
    return a;
}
#define CPASYNC16(dst, src) \
    asm volatile("cp.async.cg.shared.global [%0], [%1], 16;" :: "r"(dst), "l"(src) : "memory")
#define CPCOMMIT() asm volatile("cp.async.commit_group;" ::: "memory")
#define CPWAIT1()  asm volatile("cp.async.wait_group 1;" ::: "memory")
#define CPWAIT0()  asm volatile("cp.async.wait_group 0;" ::: "memory")
#define LDSM4(r0, r1, r2, r3, addr) \
    asm volatile("ldmatrix.sync.aligned.m8n8.x4.shared.b16 {%0,%1,%2,%3}, [%4];" \
        : "=r"(r0), "=r"(r1), "=r"(r2), "=r"(r3) : "r"(addr))

__device__ __forceinline__ void mma16(float* c, const uint32_t* a, const uint32_t* b) {
    asm volatile(
        "mma.sync.aligned.m16n8k16.row.col.f32.bf16.bf16.f32 "
        "{%0,%1,%2,%3}, {%4,%5,%6,%7}, {%8,%9}, {%0,%1,%2,%3};"
        : "+f"(c[0]), "+f"(c[1]), "+f"(c[2]), "+f"(c[3])
        : "r"(a[0]), "r"(a[1]), "r"(a[2]), "r"(a[3]), "r"(b[0]), "r"(b[1]));
}

// ---------------- fp32 -> bf16 hi/lo split ------------------------------------
__global__ void cvt_split(const float4* __restrict__ src, bf162* __restrict__ hi,
                          bf162* __restrict__ lo, int n4)
{
    int i = blockIdx.x * blockDim.x + threadIdx.x;
    if (i >= n4) return;
    float4 v = src[i];
    bf16 h0 = __float2bfloat16_rn(v.x), h1 = __float2bfloat16_rn(v.y);
    bf16 h2 = __float2bfloat16_rn(v.z), h3 = __float2bfloat16_rn(v.w);
    bf16 l0 = __float2bfloat16_rn(v.x - __bfloat162float(h0));
    bf16 l1 = __float2bfloat16_rn(v.y - __bfloat162float(h1));
    bf16 l2 = __float2bfloat16_rn(v.z - __bfloat162float(h2));
    bf16 l3 = __float2bfloat16_rn(v.w - __bfloat162float(h3));
    bf162 a; a.x = h0; a.y = h1;
    bf162 b; b.x = h2; b.y = h3;
    hi[2 * i] = a; hi[2 * i + 1] = b;
    bf162 c; c.x = l0; c.y = l1;
    bf162 d; d.x = l2; d.y = l3;
    lo[2 * i] = c; lo[2 * i + 1] = d;
}

// ============ bf16x3 mma.sync GEMM: C[M,Ncols] = sum_ph A_ph[M,K]@B_ph[n,K]^T ==
// CTA 128x128, 8 warps (2x4), warp 64x32, K-chunk 64 bf16, 2-stage cp.async.
// Phases: chunk index t -> phase t>>5 (K fixed at 2048 -> 32 chunks/phase),
// phase ph reads (A_ph, B_ph). zsplit: blockIdx.z==1 uses phases 3..5 and C1.
#define KC 64
#define PITCHB 144                 // bytes per smem row (64 bf16 + 16B pad)
#define TILEB (128 * PITCHB)       // 18432
#define STAGEB (2 * TILEB)         // 36864
#define GSMEM (2 * STAGEB)         // 73728

__global__ void __launch_bounds__(256, 2) tm_gemm(
    const bf16* __restrict__ A0, const bf16* __restrict__ A1, const bf16* __restrict__ A2,
    const bf16* __restrict__ A3, const bf16* __restrict__ A4, const bf16* __restrict__ A5,
    const bf16* __restrict__ B0, const bf16* __restrict__ B1, const bf16* __restrict__ B2,
    const bf16* __restrict__ B3, const bf16* __restrict__ B4, const bf16* __restrict__ B5,
    float* __restrict__ C0, float* __restrict__ C1,
    int nphase, int zsplit, int K, int Ncols)
{
    extern __shared__ char smc[];
    const int tid = threadIdx.x, lane = tid & 31, wid = tid >> 5;
    const int wm = wid & 1, wn = wid >> 1;
    const int r = lane >> 2, kq = lane & 3;
    const long bm = (long)blockIdx.y * 128;
    const long bn = (long)blockIdx.x * 128;

    int pbeg = 0, pcnt = nphase;
    float* C = C0;
    if (zsplit) { pcnt = 3; if (blockIdx.z) { pbeg = 3; C = C1; } }
    const int nT = pcnt * 32;            // K == 2048 -> 32 chunks per phase

    float acc[4][4][4];
#pragma unroll
    for (int i = 0; i < 4; i++)
#pragma unroll
        for (int j = 0; j < 4; j++)
#pragma unroll
            for (int t = 0; t < 4; t++) acc[i][j][t] = 0.f;

    const uint32_t sb = smem_u32(smc);

    auto getAB = [&](int t, const bf16*& a, const bf16*& b, int& k0) {
        int ph = pbeg + (t >> 5);
        k0 = (t & 31) * KC;
        switch (ph) {
            case 0: a = A0; b = B0; break;
            case 1: a = A1; b = B1; break;
            case 2: a = A2; b = B2; break;
            case 3: a = A3; b = B3; break;
            case 4: a = A4; b = B4; break;
            default: a = A5; b = B5; break;
        }
    };

    auto issue = [&](int t) {
        const bf16 *Ap, *Bp; int k0;
        getAB(t, Ap, Bp, k0);
        uint32_t As = sb + (t & 1) * STAGEB;
        uint32_t Bs = As + TILEB;
#pragma unroll
        for (int i = 0; i < 4; i++) {
            int u = tid + i * 256;
            int row = u >> 3, s = u & 7;
            CPASYNC16(As + row * PITCHB + s * 16, Ap + (bm + row) * (long)K + k0 + s * 8);
            CPASYNC16(Bs + row * PITCHB + s * 16, Bp + (bn + row) * (long)K + k0 + s * 8);
        }
        CPCOMMIT();
    };

    // ldmatrix per-lane byte offsets within a tile
    const int lm = lane >> 3, li = lane & 7;
    uint32_t aoff[4], boff[2];
#pragma unroll
    for (int mt = 0; mt < 4; mt++) {
        int arow = wm * 64 + mt * 16 + (lm & 1) * 8 + li;
        aoff[mt] = (uint32_t)(arow * PITCHB + (lm >> 1) * 16);
    }
#pragma unroll
    for (int p = 0; p < 2; p++) {
        int nt = 2 * p + (lm >> 1);
        int brow = wn * 32 + nt * 8 + li;
        boff[p] = (uint32_t)(brow * PITCHB + (lm & 1) * 16);
    }

    issue(0);
    if (nT > 1) issue(1);

    for (int t = 0; t < nT; t++) {
        if (t + 1 < nT) CPWAIT1(); else CPWAIT0();
        __syncthreads();
        uint32_t As = sb + (t & 1) * STAGEB;
        uint32_t Bs = As + TILEB;
#pragma unroll
        for (int ks = 0; ks < 4; ks++) {
            uint32_t af[4][4], bfr[2][4];
#pragma unroll
            for (int mt = 0; mt < 4; mt++)
                LDSM4(af[mt][0], af[mt][1], af[mt][2], af[mt][3], As + aoff[mt] + ks * 32);
#pragma unroll
            for (int p = 0; p < 2; p++)
                LDSM4(bfr[p][0], bfr[p][1], bfr[p][2], bfr[p][3], Bs + boff[p] + ks * 32);
#pragma unroll
            for (int mt = 0; mt < 4; mt++) {
                mma16(acc[mt][0], af[mt], &bfr[0][0]);
                mma16(acc[mt][1], af[mt], &bfr[0][2]);
                mma16(acc[mt][2], af[mt], &bfr[1][0]);
                mma16(acc[mt][3], af[mt], &bfr[1][2]);
            }
        }
        __syncthreads();
        if (t + 2 < nT) issue(t + 2);
    }

    // epilogue
#pragma unroll
    for (int mt = 0; mt < 4; mt++) {
        long row = bm + wm * 64 + mt * 16 + r;
#pragma unroll
        for (int nt = 0; nt < 4; nt++) {
            long col = bn + wn * 32 + nt * 8 + kq * 2;
            *(float2*)&C[row * (long)Ncols + col] =
                make_float2(acc[mt][nt][0], acc[mt][nt][1]);
            *(float2*)&C[(row + 8) * (long)Ncols + col] =
                make_float2(acc[mt][nt][2], acc[mt][nt][3]);
        }
    }
}

// ---------------- q softmax / k sigmoid (in-place on score buffers) -----------
__global__ void qk_act(float* __restrict__ sq, float* __restrict__ sk)
{
    int t = blockIdx.x, d = threadIdx.x;            // 128 threads
    int lane = d & 31, w = d >> 5;
    __shared__ float sm[4], ss[4];
    size_t idx = (size_t)t * DK + d;
    float v = sq[idx];
    float m = v;
#pragma unroll
    for (int o = 16; o; o >>= 1) m = fmaxf(m, __shfl_xor_sync(0xffffffffu, m, o));
    if (!lane) sm[w] = m;
    __syncthreads();
    m = fmaxf(fmaxf(sm[0], sm[1]), fmaxf(sm[2], sm[3]));
    float e = expf(v - m);
    float s = e;
#pragma unroll
    for (int o = 16; o; o >>= 1) s += __shfl_xor_sync(0xffffffffu, s, o);
    if (!lane) ss[w] = s;
    __syncthreads();
    s = ss[0] + ss[1] + ss[2] + ss[3];
    sq[idx] = e / s;
    float kv = sk[idx];
    sk[idx] = 1.f / (1.f + expf(-kv));
}

// ---------------- per-chunk decay prep (product form) -------------------------
// exp(gf) = sigmoid(-k); exp(B_i) = running product P of sigmoid(-k_j).
__global__ void chunk_prep(const float* __restrict__ q, const float* __restrict__ k)
{
    int cc = blockIdx.x;
    int d = threadIdx.x;                 // 128 threads
    __shared__ float us[CHUNK][DK];
    size_t base = (size_t)cc * CHUNK * DK + d;
    float P = 1.f;
#pragma unroll 4
    for (int i = 0; i < CHUNK; i++) {
        float kv = k[base + (size_t)i * DK];
        float u = 1.f / (1.f + expf(kv));
        us[i][d] = u;
        P *= u;
    }
    float Pl = P;
    float invs = rsqrtf(Pl);
    float sq_ = sqrtf(Pl);
    P = 1.f;
#pragma unroll 4
    for (int i = 0; i < CHUNK; i++) {
        size_t idx = base + (size_t)i * DK;
        P *= us[i][d];
        float qv = q[idx];
        float kv = k[idx];
        g_QE[idx] = qv * (P * invs);
        g_KE[idx] = kv * (sq_ / P);
        g_qb[idx] = qv * P;
        g_kd[idx] = kv * (Pl / P);
    }
    g_el[cc * DK + d] = Pl;
}

// ---------------- A = tril(QE @ KE^T) per chunk (64x64, K=128) ----------------
__global__ __launch_bounds__(256) void a_gemm()
{
    int cc = blockIdx.x;
    int tid = threadIdx.x, tx = tid & 15, ty = tid >> 4;
    __shared__ float Qs[64][33];
    __shared__ float Ks[64][33];
    float acc[4][4] = {};
    const float* Q  = g_QE + (size_t)cc * CHUNK * DK;
    const float* Kp = g_KE + (size_t)cc * CHUNK * DK;
    for (int k0 = 0; k0 < DK; k0 += 32) {
#pragma unroll
        for (int rr = 0; rr < 8; rr++) {
            int idx = tid + 256 * rr;
            int row = idx >> 5, kk = idx & 31;
            Qs[row][kk] = Q [row * DK + k0 + kk];
            Ks[row][kk] = Kp[row * DK + k0 + kk];
        }
        __syncthreads();
#pragma unroll
        for (int kk = 0; kk < 32; kk++) {
            float a[4], b[4];
#pragma unroll
            for (int i = 0; i < 4; i++) a[i] = Qs[ty * 4 + i][kk];
#pragma unroll
            for (int j = 0; j < 4; j++) b[j] = Ks[tx * 4 + j][kk];
#pragma unroll
            for (int i = 0; i < 4; i++)
#pragma unroll
                for (int j = 0; j < 4; j++) acc[i][j] = fmaf(a[i], b[j], acc[i][j]);
        }
        __syncthreads();
    }
#pragma unroll
    for (int i = 0; i < 4; i++)
#pragma unroll
        for (int j = 0; j < 4; j++) {
            int I = ty * 4 + i, J = tx * 4 + j;
            g_A[(size_t)cc * CHUNK * CHUNK + I * CHUNK + J] = (J <= I) ? acc[i][j] : 0.f;
        }
}

// ---------------- T_c[d,v] = sum_i kd[i,d] * v[i,v]   (128x2048, K=64) --------
__global__ __launch_bounds__(256) void t_gemm(const float* __restrict__ x)
{
    int cc = blockIdx.y;
    int vb = blockIdx.x * 64;
    int tid = threadIdx.x, tx = tid & 15, ty = tid >> 4;
    __shared__ __align__(16) float kds[32][132];   // [i(k)][d]
    __shared__ __align__(16) float xs[32][68];     // [i(k)][v]
    float acc[8][4] = {};
    const float* kd = g_kd + (size_t)cc * CHUNK * DK;

    for (int k0 = 0; k0 < CHUNK; k0 += 32) {
#pragma unroll
        for (int rr = 0; rr < 4; rr++) {              // kd tile 32x128
            int idx = tid + 256 * rr;
            int row = idx >> 5, seg = idx & 31;
            *(float4*)&kds[row][seg * 4] =
                *(const float4*)(kd + (size_t)(k0 + row) * DK + seg * 4);
        }
#pragma unroll
        for (int rr = 0; rr < 2; rr++) {              // v tile 32x64
            int idx = tid + 256 * rr;
            int row = idx >> 4, seg = idx & 15;
            *(float4*)&xs[row][seg * 4] =
                *(const float4*)(x + (size_t)(cc * CHUNK + k0 + row) * HID + vb + seg * 4);
        }
        __syncthreads();
#pragma unroll
        for (int kk = 0; kk < 32; kk++) {
            float a[8], b[4];
            *(float4*)&a[0] = *(float4*)&kds[kk][ty * 8];
            *(float4*)&a[4] = *(float4*)&kds[kk][ty * 8 + 4];
            *(float4*)&b[0] = *(float4*)&xs[kk][tx * 4];
#pragma unroll
            for (int i = 0; i < 8; i++)
#pragma unroll
                for (int j = 0; j < 4; j++) acc[i][j] = fmaf(a[i], b[j], acc[i][j]);
        }
        __syncthreads();
    }
    float* T = g_T + (size_t)cc * DK * HID;
#pragma unroll
    for (int i = 0; i < 8; i++) {
        float4 o4 = make_float4(acc[i][0], acc[i][1], acc[i][2], acc[i][3]);
        *(float4*)(T + (size_t)(ty * 8 + i) * HID + vb + tx * 4) = o4;
    }
}

// ---------------- chunk-state scan: in-place T -> S_before --------------------
__global__ void scan_k()
{
    int gid = blockIdx.x * blockDim.x + threadIdx.x;   // 131072 threads
    int vg = gid & 511;
    int rest = gid >> 9;
    int d = rest & 127;
    int b = rest >> 7;
    float4 s = make_float4(0.f, 0.f, 0.f, 0.f);
    for (int c = 0; c < NCHUNK; c++) {
        int cc = b * NCHUNK + c;
        float e = g_el[cc * DK + d];
        float4* p = (float4*)&g_T[((size_t)cc * DK + d) * HID + vg * 4];
        float4 t = *p;
        *p = s;                                        // S before chunk c
        s.x = fmaf(s.x, e, t.x);
        s.y = fmaf(s.y, e, t.y);
        s.z = fmaf(s.z, e, t.z);
        s.w = fmaf(s.w, e, t.w);
    }
}

// ---------------- o = A @ v + qb @ S_before (64x2048 per chunk) ---------------
// Writes o fp32 + bf16 hi/lo split (A operand of the gate GEMM).
__global__ __launch_bounds__(256) void o_gemm(const float* __restrict__ x)
{
    int cc = blockIdx.y;
    int vb = blockIdx.x * 64;
    int tid = threadIdx.x, tx = tid & 15, ty = tid >> 4;
    __shared__ float Ls[64][33];
    __shared__ float Rs[32][65];
    float acc[4][4] = {};

    for (int ph = 0; ph < 2; ph++) {
        int KK = ph ? DK : CHUNK;
        const float* L = ph ? (g_qb + (size_t)cc * CHUNK * DK)
                            : (g_A + (size_t)cc * CHUNK * CHUNK);
        int lstride = ph ? DK : CHUNK;
        for (int k0 = 0; k0 < KK; k0 += 32) {
#pragma unroll
            for (int rr = 0; rr < 8; rr++) {          // LHS tile 64x32
                int idx = tid + 256 * rr;
                int row = idx >> 5, kk = idx & 31;
                Ls[row][kk] = L[(size_t)row * lstride + k0 + kk];
            }
#pragma unroll
            for (int rr = 0; rr < 8; rr++) {          // RHS tile 32x64
                int idx = tid + 256 * rr;
                int kk = idx >> 6, v = idx & 63;
                float val;
                if (ph == 0)
                    val = x[(size_t)(cc * CHUNK + k0 + kk) * HID + vb + v];
                else
                    val = g_T[(size_t)cc * DK * HID + (size_t)(k0 + kk) * HID + vb + v];
                Rs[kk][v] = val;
            }
            __syncthreads();
#pragma unroll
            for (int kk = 0; kk < 32; kk++) {
                float a[4], b[4];
#pragma unroll
                for (int i = 0; i < 4; i++) a[i] = Ls[ty * 4 + i][kk];
#pragma unroll
                for (int j = 0; j < 4; j++) b[j] = Rs[kk][tx * 4 + j];
#pragma unroll
                for (int i = 0; i < 4; i++)
#pragma unroll
                    for (int j = 0; j < 4; j++) acc[i][j] = fmaf(a[i], b[j], acc[i][j]);
            }
            __syncthreads();
        }
    }
#pragma unroll
    for (int i = 0; i < 4; i++) {
        size_t rowel = (size_t)(cc * CHUNK + ty * 4 + i) * HID + vb + tx * 4;
        float4 v = make_float4(acc[i][0], acc[i][1], acc[i][2], acc[i][3]);
        *(float4*)&g_o[rowel] = v;
        bf16 h0 = __float2bfloat16_rn(v.x), h1 = __float2bfloat16_rn(v.y);
        bf16 h2 = __float2bfloat16_rn(v.z), h3 = __float2bfloat16_rn(v.w);
        bf162 p0; p0.x = h0; p0.y = h1;
        bf162 p1; p1.x = h2; p1.y = h3;
        *(bf162*)&g_oh[rowel] = p0;
        *(bf162*)&g_oh[rowel + 2] = p1;
        bf162 q0, q1;
        q0.x = __float2bfloat16_rn(v.x - __bfloat162float(h0));
        q0.y = __float2bfloat16_rn(v.y - __bfloat162float(h1));
        q1.x = __float2bfloat16_rn(v.z - __bfloat162float(h2));
        q1.y = __float2bfloat16_rn(v.w - __bfloat162float(h3));
        *(bf162*)&g_ol[rowel] = q0;
        *(bf162*)&g_ol[rowel + 2] = q1;
    }
}

// ---------------- t = rmsnorm(o)*gw * silu(G) -> bf16 hi/lo -------------------
__global__ __launch_bounds__(256) void gate_norm(const float* __restrict__ o,
                                                 const float* __restrict__ G,
                                                 const float* __restrict__ gw,
                                                 bf16* __restrict__ th,
                                                 bf16* __restrict__ tl)
{
    int t = blockIdx.x, tid = threadIdx.x;
    int lane = tid & 31, w = tid >> 5;
    const float2* o2 = (const float2*)(o + (size_t)t * HID);
    const float2* G2 = (const float2*)(G + (size_t)t * HID);
    const float2* w2 = (const float2*)gw;
    float s = 0.f;
#pragma unroll
    for (int j = 0; j < 4; j++) {
        float2 v = o2[tid + j * 256];
        s = fmaf(v.x, v.x, s); s = fmaf(v.y, v.y, s);
    }
#pragma unroll
    for (int off = 16; off; off >>= 1) s += __shfl_xor_sync(0xffffffffu, s, off);
    __shared__ float red[8];
    if (!lane) red[w] = s;
    __syncthreads();
    float tot = 0.f;
#pragma unroll
    for (int i = 0; i < 8; i++) tot += red[i];
    float rr = rsqrtf(tot * (1.0f / HID) + 1e-5f);
    bf162* th2 = (bf162*)(th + (size_t)t * HID);
    bf162* tl2 = (bf162*)(tl + (size_t)t * HID);
#pragma unroll
    for (int j = 0; j < 4; j++) {
        int idx = tid + j * 256;
        float2 ov = o2[idx], gv = G2[idx], wv = w2[idx];
        float t0 = ov.x * rr * wv.x * (gv.x / (1.f + expf(-gv.x)));
        float t1 = ov.y * rr * wv.y * (gv.y / (1.f + expf(-gv.y)));
        bf16 h0 = __float2bfloat16_rn(t0), h1 = __float2bfloat16_rn(t1);
        bf162 hp; hp.x = h0; hp.y = h1;
        th2[idx] = hp;
        bf162 lp;
        lp.x = __float2bfloat16_rn(t0 - __bfloat162float(h0));
        lp.y = __float2bfloat16_rn(t1 - __bfloat162float(h1));
        tl2[idx] = lp;
    }
}

// ---------------- launch ------------------------------------------------------
extern "C" void kernel_launch(void* const* d_in, const int* in_sizes, int n_in,
                              void* d_out, int out_size)
{
    const float* x   = (const float*)d_in[0];
    const float* Wq  = (const float*)d_in[1];
    const float* Wk  = (const float*)d_in[2];
    const float* Wog = (const float*)d_in[3];
    const float* Wig = (const float*)d_in[4];
    const float* Wo  = (const float*)d_in[5];
    const float* gw  = (const float*)d_in[6];
    float* out = (float*)d_out;

    float *sq, *sk, *o_, *G;
    cudaGetSymbolAddress((void**)&sq, g_sq);
    cudaGetSymbolAddress((void**)&sk, g_sk);
    cudaGetSymbolAddress((void**)&o_, g_o);
    cudaGetSymbolAddress((void**)&G,  g_G);
    bf16 *xh, *xl, *wqh, *wql, *wkh, *wkl, *wogh, *wogl, *wigh, *wigl, *woh, *wol;
    bf16 *oh, *ol, *th, *tl;
    cudaGetSymbolAddress((void**)&xh, g_xh);   cudaGetSymbolAddress((void**)&xl, g_xl);
    cudaGetSymbolAddress((void**)&wqh, g_wqh); cudaGetSymbolAddress((void**)&wql, g_wql);
    cudaGetSymbolAddress((void**)&wkh, g_wkh); cudaGetSymbolAddress((void**)&wkl, g_wkl);
    cudaGetSymbolAddress((void**)&wogh, g_wogh); cudaGetSymbolAddress((void**)&wogl, g_wogl);
    cudaGetSymbolAddress((void**)&wigh, g_wigh); cudaGetSymbolAddress((void**)&wigl, g_wigl);
    cudaGetSymbolAddress((void**)&woh, g_woh); cudaGetSymbolAddress((void**)&wol, g_wol);
    cudaGetSymbolAddress((void**)&oh, g_oh);   cudaGetSymbolAddress((void**)&ol, g_ol);
    cudaGetSymbolAddress((void**)&th, g_th);   cudaGetSymbolAddress((void**)&tl, g_tl);

    cudaFuncSetAttribute(tm_gemm, cudaFuncAttributeMaxDynamicSharedMemorySize, GSMEM);

    // 0. hi/lo splits of x and weights
    const int XN4 = NTOK * HID / 4, WN4 = HID * HID / 4, PN4 = DK * HID / 4;
    cvt_split<<<XN4 / 256, 256>>>((const float4*)x, (bf162*)xh, (bf162*)xl, XN4);
    cvt_split<<<PN4 / 256, 256>>>((const float4*)Wq, (bf162*)wqh, (bf162*)wql, PN4);
    cvt_split<<<PN4 / 256, 256>>>((const float4*)Wk, (bf162*)wkh, (bf162*)wkl, PN4);
    cvt_split<<<WN4 / 256, 256>>>((const float4*)Wog, (bf162*)wogh, (bf162*)wogl, WN4);
    cvt_split<<<WN4 / 256, 256>>>((const float4*)Wig, (bf162*)wigh, (bf162*)wigl, WN4);
    cvt_split<<<WN4 / 256, 256>>>((const float4*)Wo, (bf162*)woh, (bf162*)wol, WN4);

    // 1. q,k projections fused (z selects Wq->sq vs Wk->sk), bf16x3 phases
    tm_gemm<<<dim3(1, NTOK / 128, 2), 256, GSMEM>>>(
        xh, xl, xh, xh, xl, xh,
        wqh, wqh, wql, wkh, wkh, wkl,
        sq, sk, 3, 1, HID, DK);
    // 2. softmax / sigmoid
    qk_act<<<NTOK, DK>>>(sq, sk);
    // 3. per-chunk decay factors
    chunk_prep<<<NCC, DK>>>(sq, sk);
    // 4. intra-chunk matrices
    a_gemm<<<NCC, 256>>>();
    // 5. per-chunk state contributions T_c
    t_gemm<<<dim3(HID / 64, NCC), 256>>>(x);
    // 6. recurrent scan (in-place: T -> S_before)
    scan_k<<<512, 256>>>();
    // 7. o = A@v + qb@S_before (+ bf16 hi/lo epilogue)
    o_gemm<<<dim3(HID / 64, NCC), 256>>>(x);
    // 8. gates: G = o@Wog^T + x@Wig^T as 6 bf16 phases
    tm_gemm<<<dim3(HID / 128, NTOK / 128, 1), 256, GSMEM>>>(
        oh, ol, oh, xh, xl, xh,
        wogh, wogh, wogl, wigh, wigh, wigl,
        G, G, 6, 0, HID, HID);
    // 9. rmsnorm + silu gating -> t hi/lo
    gate_norm<<<NTOK, 256>>>(o_, G, gw, th, tl);
    // 10. final projection: out = t @ Wo^T, bf16x3
    tm_gemm<<<dim3(HID / 128, NTOK / 128, 1), 256, GSMEM>>>(
        th, tl, th, th, tl, th,
        woh, woh, wol, woh, woh, wol,
        out, out, 3, 0, HID, HID);
}

// round 7
// speedup vs baseline: 2.7910x; 1.0254x over previous
#include <cuda_runtime.h>
#include <cuda_bf16.h>
#include <cstdint>
#include <math.h>

// Problem constants
#define BATCH 2
#define SEQ   4096
#define HID   2048
#define DK    128
#define CHUNK 64
#define NCHUNK 64                  // per batch
#define NCC   (BATCH*NCHUNK)       // 128 total batch-chunks
#define NTOK  (BATCH*SEQ)          // 8192

typedef __nv_bfloat16  bf16;
typedef __nv_bfloat162 bf162;

// ---------------- fp32 scratch ------------------------------------------------
__device__ float g_sq[(size_t)NTOK*DK];         // q scores -> q (softmax)
__device__ float g_sk[(size_t)NTOK*DK];         // k scores -> k (sigmoid)
__device__ float g_QE[(size_t)NCC*CHUNK*DK];    // q * exp(B - Bm)
__device__ float g_KE[(size_t)NCC*CHUNK*DK];    // k * exp(Bm - B)
__device__ float g_qb[(size_t)NCC*CHUNK*DK];    // q * exp(B)
__device__ float g_kd[(size_t)NCC*CHUNK*DK];    // k * exp(Blast - B)
__device__ float g_el[NCC*DK];                  // exp(Blast)
__device__ float g_A [(size_t)NCC*CHUNK*CHUNK]; // tril intra matrices
__device__ float g_T [(size_t)NCC*DK*HID];      // T_c then (in-place) S_before_c
__device__ float g_o [(size_t)NTOK*HID];        // attention output o (fp32)
__device__ float g_G [(size_t)NTOK*HID];        // gate scores

// ---------------- bf16 hi/lo scratch ------------------------------------------
__device__ __align__(16) bf16 g_xh [(size_t)NTOK*HID];
__device__ __align__(16) bf16 g_xl [(size_t)NTOK*HID];
__device__ __align__(16) bf16 g_wqh[(size_t)DK*HID];
__device__ __align__(16) bf16 g_wql[(size_t)DK*HID];
__device__ __align__(16) bf16 g_wkh[(size_t)DK*HID];
__device__ __align__(16) bf16 g_wkl[(size_t)DK*HID];
__device__ __align__(16) bf16 g_wogh[(size_t)HID*HID];
__device__ __align__(16) bf16 g_wogl[(size_t)HID*HID];
__device__ __align__(16) bf16 g_wigh[(size_t)HID*HID];
__device__ __align__(16) bf16 g_wigl[(size_t)HID*HID];
__device__ __align__(16) bf16 g_woh[(size_t)HID*HID];
__device__ __align__(16) bf16 g_wol[(size_t)HID*HID];
__device__ __align__(16) bf16 g_oh [(size_t)NTOK*HID];
__device__ __align__(16) bf16 g_ol [(size_t)NTOK*HID];
__device__ __align__(16) bf16 g_th [(size_t)NTOK*HID];
__device__ __align__(16) bf16 g_tl [(size_t)NTOK*HID];

// ---------------- helpers -----------------------------------------------------
__device__ __forceinline__ uint32_t smem_u32(const void* p) {
    uint32_t a;
    asm("{ .reg .u64 t; cvta.to.shared.u64 t, %1; cvt.u32.u64 %0, t; }" : "=r"(a) : "l"(p));
    return a;
}
#define CPASYNC16(dst, src) \
    asm volatile("cp.async.cg.shared.global [%0], [%1], 16;" :: "r"(dst), "l"(src) : "memory")
#define CPCOMMIT() asm volatile("cp.async.commit_group;" ::: "memory")
#define CPWAIT1()  asm volatile("cp.async.wait_group 1;" ::: "memory")
#define CPWAIT0()  asm volatile("cp.async.wait_group 0;" ::: "memory")
#define LDSM4(r0, r1, r2, r3, addr) \
    asm volatile("ldmatrix.sync.aligned.m8n8.x4.shared.b16 {%0,%1,%2,%3}, [%4];" \
        : "=r"(r0), "=r"(r1), "=r"(r2), "=r"(r3) : "r"(addr))

__device__ __forceinline__ void mma16(float* c, const uint32_t* a, const uint32_t* b) {
    asm volatile(
        "mma.sync.aligned.m16n8k16.row.col.f32.bf16.bf16.f32 "
        "{%0,%1,%2,%3}, {%4,%5,%6,%7}, {%8,%9}, {%0,%1,%2,%3};"
        : "+f"(c[0]), "+f"(c[1]), "+f"(c[2]), "+f"(c[3])
        : "r"(a[0]), "r"(a[1]), "r"(a[2]), "r"(a[3]), "r"(b[0]), "r"(b[1]));
}

// ---------------- fp32 -> bf16 hi/lo split ------------------------------------
__device__ __forceinline__ void split4(float4 v, bf162* hi, bf162* lo, size_t i2)
{
    bf16 h0 = __float2bfloat16_rn(v.x), h1 = __float2bfloat16_rn(v.y);
    bf16 h2 = __float2bfloat16_rn(v.z), h3 = __float2bfloat16_rn(v.w);
    bf162 a; a.x = h0; a.y = h1;
    bf162 b; b.x = h2; b.y = h3;
    hi[i2] = a; hi[i2 + 1] = b;
    bf162 c, d;
    c.x = __float2bfloat16_rn(v.x - __bfloat162float(h0));
    c.y = __float2bfloat16_rn(v.y - __bfloat162float(h1));
    d.x = __float2bfloat16_rn(v.z - __bfloat162float(h2));
    d.y = __float2bfloat16_rn(v.w - __bfloat162float(h3));
    lo[i2] = c; lo[i2 + 1] = d;
}

__global__ void cvt_split(const float4* __restrict__ src, bf162* __restrict__ hi,
                          bf162* __restrict__ lo, int n4)
{
    int i = blockIdx.x * blockDim.x + threadIdx.x;
    if (i >= n4) return;
    split4(src[i], hi, lo, (size_t)2 * i);
}

// two tensors in one launch (blockIdx.y selects)
__global__ void cvt_split2(const float4* __restrict__ s0, bf162* __restrict__ h0,
                           bf162* __restrict__ l0,
                           const float4* __restrict__ s1, bf162* __restrict__ h1,
                           bf162* __restrict__ l1, int n4)
{
    int i = blockIdx.x * blockDim.x + threadIdx.x;
    if (i >= n4) return;
    if (blockIdx.y == 0) split4(s0[i], h0, l0, (size_t)2 * i);
    else                 split4(s1[i], h1, l1, (size_t)2 * i);
}

// ============ bf16x3 mma.sync GEMM: C[M,Ncols] = sum_ph A_ph[M,K]@B_ph[n,K]^T ==
// CTA 128x128, 8 warps (2x4), warp 64x32, K-chunk 64 bf16.
// 3-stage cp.async pipeline, single __syncthreads per chunk (CUTLASS multistage
// order: wait -> barrier -> prefetch t+2 -> compute t). Phase t>>5 selects the
// (A,B) operand pair; zsplit: blockIdx.z==1 uses phases 3..5 and C1.
#define KC 64
#define PITCHB 144                 // bytes per smem row (64 bf16 + 16B pad)
#define TILEB (128 * PITCHB)       // 18432
#define STAGEB (2 * TILEB)         // 36864 (A tile + B tile)
#define NSTG 3
#define GSMEM (NSTG * STAGEB)      // 110592

__global__ void __launch_bounds__(256, 2) tm_gemm(
    const bf16* __restrict__ A0, const bf16* __restrict__ A1, const bf16* __restrict__ A2,
    const bf16* __restrict__ A3, const bf16* __restrict__ A4, const bf16* __restrict__ A5,
    const bf16* __restrict__ B0, const bf16* __restrict__ B1, const bf16* __restrict__ B2,
    const bf16* __restrict__ B3, const bf16* __restrict__ B4, const bf16* __restrict__ B5,
    float* __restrict__ C0, float* __restrict__ C1,
    int nphase, int zsplit, int K, int Ncols)
{
    extern __shared__ char smc[];
    const int tid = threadIdx.x, lane = tid & 31, wid = tid >> 5;
    const int wm = wid & 1, wn = wid >> 1;
    const int r = lane >> 2, kq = lane & 3;
    const long bm = (long)blockIdx.y * 128;
    const long bn = (long)blockIdx.x * 128;

    int pbeg = 0, pcnt = nphase;
    float* C = C0;
    if (zsplit) { pcnt = 3; if (blockIdx.z) { pbeg = 3; C = C1; } }
    const int nT = pcnt * 32;            // K == 2048 -> 32 chunks per phase

    float acc[4][4][4];
#pragma unroll
    for (int i = 0; i < 4; i++)
#pragma unroll
        for (int j = 0; j < 4; j++)
#pragma unroll
            for (int t = 0; t < 4; t++) acc[i][j][t] = 0.f;

    const uint32_t sb = smem_u32(smc);

    auto getAB = [&](int t, const bf16*& a, const bf16*& b, int& k0) {
        int ph = pbeg + (t >> 5);
        k0 = (t & 31) * KC;
        switch (ph) {
            case 0: a = A0; b = B0; break;
            case 1: a = A1; b = B1; break;
            case 2: a = A2; b = B2; break;
            case 3: a = A3; b = B3; break;
            case 4: a = A4; b = B4; break;
            default: a = A5; b = B5; break;
        }
    };

    auto issue = [&](int t, int stg) {
        const bf16 *Ap, *Bp; int k0;
        getAB(t, Ap, Bp, k0);
        uint32_t As = sb + stg * STAGEB;
        uint32_t Bs = As + TILEB;
#pragma unroll
        for (int i = 0; i < 4; i++) {
            int u = tid + i * 256;
            int row = u >> 3, s = u & 7;
            CPASYNC16(As + row * PITCHB + s * 16, Ap + (bm + row) * (long)K + k0 + s * 8);
            CPASYNC16(Bs + row * PITCHB + s * 16, Bp + (bn + row) * (long)K + k0 + s * 8);
        }
        CPCOMMIT();
    };

    // ldmatrix per-lane byte offsets within a tile
    const int lm = lane >> 3, li = lane & 7;
    uint32_t aoff[4], boff[2];
#pragma unroll
    for (int mt = 0; mt < 4; mt++) {
        int arow = wm * 64 + mt * 16 + (lm & 1) * 8 + li;
        aoff[mt] = (uint32_t)(arow * PITCHB + (lm >> 1) * 16);
    }
#pragma unroll
    for (int p = 0; p < 2; p++) {
        int nt = 2 * p + (lm >> 1);
        int brow = wn * 32 + nt * 8 + li;
        boff[p] = (uint32_t)(brow * PITCHB + (lm & 1) * 16);
    }

    issue(0, 0);
    issue(1, 1);

    int st = 0, ist = 2;                 // compute stage / prefetch stage
    for (int t = 0; t < nT; t++) {
        if (t == nT - 1) CPWAIT0(); else CPWAIT1();
        __syncthreads();                 // stage t visible; stage ist free
        if (t + 2 < nT) issue(t + 2, ist);
        uint32_t As = sb + st * STAGEB;
        uint32_t Bs = As + TILEB;
#pragma unroll
        for (int ks = 0; ks < 4; ks++) {
            uint32_t af[4][4], bfr[2][4];
#pragma unroll
            for (int mt = 0; mt < 4; mt++)
                LDSM4(af[mt][0], af[mt][1], af[mt][2], af[mt][3], As + aoff[mt] + ks * 32);
#pragma unroll
            for (int p = 0; p < 2; p++)
                LDSM4(bfr[p][0], bfr[p][1], bfr[p][2], bfr[p][3], Bs + boff[p] + ks * 32);
#pragma unroll
            for (int mt = 0; mt < 4; mt++) {
                mma16(acc[mt][0], af[mt], &bfr[0][0]);
                mma16(acc[mt][1], af[mt], &bfr[0][2]);
                mma16(acc[mt][2], af[mt], &bfr[1][0]);
                mma16(acc[mt][3], af[mt], &bfr[1][2]);
            }
        }
        st = (st == NSTG - 1) ? 0 : st + 1;
        ist = (ist == NSTG - 1) ? 0 : ist + 1;
    }

    // epilogue
#pragma unroll
    for (int mt = 0; mt < 4; mt++) {
        long row = bm + wm * 64 + mt * 16 + r;
#pragma unroll
        for (int nt = 0; nt < 4; nt++) {
            long col = bn + wn * 32 + nt * 8 + kq * 2;
            *(float2*)&C[row * (long)Ncols + col] =
                make_float2(acc[mt][nt][0], acc[mt][nt][1]);
            *(float2*)&C[(row + 8) * (long)Ncols + col] =
                make_float2(acc[mt][nt][2], acc[mt][nt][3]);
        }
    }
}

// ---------------- q softmax / k sigmoid (in-place on score buffers) -----------
__global__ void qk_act(float* __restrict__ sq, float* __restrict__ sk)
{
    int t = blockIdx.x, d = threadIdx.x;            // 128 threads
    int lane = d & 31, w = d >> 5;
    __shared__ float sm[4], ss[4];
    size_t idx = (size_t)t * DK + d;
    float v = sq[idx];
    float m = v;
#pragma unroll
    for (int o = 16; o; o >>= 1) m = fmaxf(m, __shfl_xor_sync(0xffffffffu, m, o));
    if (!lane) sm[w] = m;
    __syncthreads();
    m = fmaxf(fmaxf(sm[0], sm[1]), fmaxf(sm[2], sm[3]));
    float e = expf(v - m);
    float s = e;
#pragma unroll
    for (int o = 16; o; o >>= 1) s += __shfl_xor_sync(0xffffffffu, s, o);
    if (!lane) ss[w] = s;
    __syncthreads();
    s = ss[0] + ss[1] + ss[2] + ss[3];
    sq[idx] = e / s;
    float kv = sk[idx];
    sk[idx] = 1.f / (1.f + expf(-kv));
}

// ---------------- per-chunk decay prep (product form) -------------------------
// exp(gf) = sigmoid(-k); exp(B_i) = running product P of sigmoid(-k_j).
__global__ void chunk_prep(const float* __restrict__ q, const float* __restrict__ k)
{
    int cc = blockIdx.x;
    int d = threadIdx.x;                 // 128 threads
    __shared__ float us[CHUNK][DK];
    size_t base = (size_t)cc * CHUNK * DK + d;
    float P = 1.f;
#pragma unroll 4
    for (int i = 0; i < CHUNK; i++) {
        float kv = k[base + (size_t)i * DK];
        float u = 1.f / (1.f + expf(kv));
        us[i][d] = u;
        P *= u;
    }
    float Pl = P;
    float invs = rsqrtf(Pl);
    float sq_ = sqrtf(Pl);
    P = 1.f;
#pragma unroll 4
    for (int i = 0; i < CHUNK; i++) {
        size_t idx = base + (size_t)i * DK;
        P *= us[i][d];
        float qv = q[idx];
        float kv = k[idx];
        g_QE[idx] = qv * (P * invs);
        g_KE[idx] = kv * (sq_ / P);
        g_qb[idx] = qv * P;
        g_kd[idx] = kv * (Pl / P);
    }
    g_el[cc * DK + d] = Pl;
}

// ---------------- A = tril(QE @ KE^T) per chunk (64x64, K=128) ----------------
__global__ __launch_bounds__(256) void a_gemm()
{
    int cc = blockIdx.x;
    int tid = threadIdx.x, tx = tid & 15, ty = tid >> 4;
    __shared__ float Qs[64][33];
    __shared__ float Ks[64][33];
    float acc[4][4] = {};
    const float* Q  = g_QE + (size_t)cc * CHUNK * DK;
    const float* Kp = g_KE + (size_t)cc * CHUNK * DK;
    for (int k0 = 0; k0 < DK; k0 += 32) {
#pragma unroll
        for (int rr = 0; rr < 8; rr++) {
            int idx = tid + 256 * rr;
            int row = idx >> 5, kk = idx & 31;
            Qs[row][kk] = Q [row * DK + k0 + kk];
            Ks[row][kk] = Kp[row * DK + k0 + kk];
        }
        __syncthreads();
#pragma unroll
        for (int kk = 0; kk < 32; kk++) {
            float a[4], b[4];
#pragma unroll
            for (int i = 0; i < 4; i++) a[i] = Qs[ty * 4 + i][kk];
#pragma unroll
            for (int j = 0; j < 4; j++) b[j] = Ks[tx * 4 + j][kk];
#pragma unroll
            for (int i = 0; i < 4; i++)
#pragma unroll
                for (int j = 0; j < 4; j++) acc[i][j] = fmaf(a[i], b[j], acc[i][j]);
        }
        __syncthreads();
    }
#pragma unroll
    for (int i = 0; i < 4; i++)
#pragma unroll
        for (int j = 0; j < 4; j++) {
            int I = ty * 4 + i, J = tx * 4 + j;
            g_A[(size_t)cc * CHUNK * CHUNK + I * CHUNK + J] = (J <= I) ? acc[i][j] : 0.f;
        }
}

// ---------------- T_c[d,v] = sum_i kd[i,d] * v[i,v]   (128x2048, K=64) --------
__global__ __launch_bounds__(256) void t_gemm(const float* __restrict__ x)
{
    int cc = blockIdx.y;
    int vb = blockIdx.x * 64;
    int tid = threadIdx.x, tx = tid & 15, ty = tid >> 4;
    __shared__ __align__(16) float kds[32][132];   // [i(k)][d]
    __shared__ __align__(16) float xs[32][68];     // [i(k)][v]
    float acc[8][4] = {};
    const float* kd = g_kd + (size_t)cc * CHUNK * DK;

    for (int k0 = 0; k0 < CHUNK; k0 += 32) {
#pragma unroll
        for (int rr = 0; rr < 4; rr++) {              // kd tile 32x128
            int idx = tid + 256 * rr;
            int row = idx >> 5, seg = idx & 31;
            *(float4*)&kds[row][seg * 4] =
                *(const float4*)(kd + (size_t)(k0 + row) * DK + seg * 4);
        }
#pragma unroll
        for (int rr = 0; rr < 2; rr++) {              // v tile 32x64
            int idx = tid + 256 * rr;
            int row = idx >> 4, seg = idx & 15;
            *(float4*)&xs[row][seg * 4] =
                *(const float4*)(x + (size_t)(cc * CHUNK + k0 + row) * HID + vb + seg * 4);
        }
        __syncthreads();
#pragma unroll
        for (int kk = 0; kk < 32; kk++) {
            float a[8], b[4];
            *(float4*)&a[0] = *(float4*)&kds[kk][ty * 8];
            *(float4*)&a[4] = *(float4*)&kds[kk][ty * 8 + 4];
            *(float4*)&b[0] = *(float4*)&xs[kk][tx * 4];
#pragma unroll
            for (int i = 0; i < 8; i++)
#pragma unroll
                for (int j = 0; j < 4; j++) acc[i][j] = fmaf(a[i], b[j], acc[i][j]);
        }
        __syncthreads();
    }
    float* T = g_T + (size_t)cc * DK * HID;
#pragma unroll
    for (int i = 0; i < 8; i++) {
        float4 o4 = make_float4(acc[i][0], acc[i][1], acc[i][2], acc[i][3]);
        *(float4*)(T + (size_t)(ty * 8 + i) * HID + vb + tx * 4) = o4;
    }
}

// ---------------- chunk-state scan: in-place T -> S_before --------------------
__global__ void scan_k()
{
    int gid = blockIdx.x * blockDim.x + threadIdx.x;   // 131072 threads
    int vg = gid & 511;
    int rest = gid >> 9;
    int d = rest & 127;
    int b = rest >> 7;
    float4 s = make_float4(0.f, 0.f, 0.f, 0.f);
    for (int c = 0; c < NCHUNK; c++) {
        int cc = b * NCHUNK + c;
        float e = g_el[cc * DK + d];
        float4* p = (float4*)&g_T[((size_t)cc * DK + d) * HID + vg * 4];
        float4 t = *p;
        *p = s;                                        // S before chunk c
        s.x = fmaf(s.x, e, t.x);
        s.y = fmaf(s.y, e, t.y);
        s.z = fmaf(s.z, e, t.z);
        s.w = fmaf(s.w, e, t.w);
    }
}

// ---------------- o = A @ v + qb @ S_before (64x2048 per chunk) ---------------
// Writes o fp32 + bf16 hi/lo split (A operand of the gate GEMM).
__global__ __launch_bounds__(256) void o_gemm(const float* __restrict__ x)
{
    int cc = blockIdx.y;
    int vb = blockIdx.x * 64;
    int tid = threadIdx.x, tx = tid & 15, ty = tid >> 4;
    __shared__ float Ls[64][33];
    __shared__ float Rs[32][65];
    float acc[4][4] = {};

    for (int ph = 0; ph < 2; ph++) {
        int KK = ph ? DK : CHUNK;
        const float* L = ph ? (g_qb + (size_t)cc * CHUNK * DK)
                            : (g_A + (size_t)cc * CHUNK * CHUNK);
        int lstride = ph ? DK : CHUNK;
        for (int k0 = 0; k0 < KK; k0 += 32) {
#pragma unroll
            for (int rr = 0; rr < 8; rr++) {          // LHS tile 64x32
                int idx = tid + 256 * rr;
                int row = idx >> 5, kk = idx & 31;
                Ls[row][kk] = L[(size_t)row * lstride + k0 + kk];
            }
#pragma unroll
            for (int rr = 0; rr < 8; rr++) {          // RHS tile 32x64
                int idx = tid + 256 * rr;
                int kk = idx >> 6, v = idx & 63;
                float val;
                if (ph == 0)
                    val = x[(size_t)(cc * CHUNK + k0 + kk) * HID + vb + v];
                else
                    val = g_T[(size_t)cc * DK * HID + (size_t)(k0 + kk) * HID + vb + v];
                Rs[kk][v] = val;
            }
            __syncthreads();
#pragma unroll
            for (int kk = 0; kk < 32; kk++) {
                float a[4], b[4];
#pragma unroll
                for (int i = 0; i < 4; i++) a[i] = Ls[ty * 4 + i][kk];
#pragma unroll
                for (int j = 0; j < 4; j++) b[j] = Rs[kk][tx * 4 + j];
#pragma unroll
                for (int i = 0; i < 4; i++)
#pragma unroll
                    for (int j = 0; j < 4; j++) acc[i][j] = fmaf(a[i], b[j], acc[i][j]);
            }
            __syncthreads();
        }
    }
#pragma unroll
    for (int i = 0; i < 4; i++) {
        size_t rowel = (size_t)(cc * CHUNK + ty * 4 + i) * HID + vb + tx * 4;
        float4 v = make_float4(acc[i][0], acc[i][1], acc[i][2], acc[i][3]);
        *(float4*)&g_o[rowel] = v;
        bf16 h0 = __float2bfloat16_rn(v.x), h1 = __float2bfloat16_rn(v.y);
        bf16 h2 = __float2bfloat16_rn(v.z), h3 = __float2bfloat16_rn(v.w);
        bf162 p0; p0.x = h0; p0.y = h1;
        bf162 p1; p1.x = h2; p1.y = h3;
        *(bf162*)&g_oh[rowel] = p0;
        *(bf162*)&g_oh[rowel + 2] = p1;
        bf162 q0, q1;
        q0.x = __float2bfloat16_rn(v.x - __bfloat162float(h0));
        q0.y = __float2bfloat16_rn(v.y - __bfloat162float(h1));
        q1.x = __float2bfloat16_rn(v.z - __bfloat162float(h2));
        q1.y = __float2bfloat16_rn(v.w - __bfloat162float(h3));
        *(bf162*)&g_ol[rowel] = q0;
        *(bf162*)&g_ol[rowel + 2] = q1;
    }
}

// ---------------- t = rmsnorm(o)*gw * silu(G) -> bf16 hi/lo -------------------
__global__ __launch_bounds__(256) void gate_norm(const float* __restrict__ o,
                                                 const float* __restrict__ G,
                                                 const float* __restrict__ gw,
                                                 bf16* __restrict__ th,
                                                 bf16* __restrict__ tl)
{
    int t = blockIdx.x, tid = threadIdx.x;
    int lane = tid & 31, w = tid >> 5;
    const float2* o2 = (const float2*)(o + (size_t)t * HID);
    const float2* G2 = (const float2*)(G + (size_t)t * HID);
    const float2* w2 = (const float2*)gw;
    float s = 0.f;
#pragma unroll
    for (int j = 0; j < 4; j++) {
        float2 v = o2[tid + j * 256];
        s = fmaf(v.x, v.x, s); s = fmaf(v.y, v.y, s);
    }
#pragma unroll
    for (int off = 16; off; off >>= 1) s += __shfl_xor_sync(0xffffffffu, s, off);
    __shared__ float red[8];
    if (!lane) red[w] = s;
    __syncthreads();
    float tot = 0.f;
#pragma unroll
    for (int i = 0; i < 8; i++) tot += red[i];
    float rr = rsqrtf(tot * (1.0f / HID) + 1e-5f);
    bf162* th2 = (bf162*)(th + (size_t)t * HID);
    bf162* tl2 = (bf162*)(tl + (size_t)t * HID);
#pragma unroll
    for (int j = 0; j < 4; j++) {
        int idx = tid + j * 256;
        float2 ov = o2[idx], gv = G2[idx], wv = w2[idx];
        float t0 = ov.x * rr * wv.x * (gv.x / (1.f + expf(-gv.x)));
        float t1 = ov.y * rr * wv.y * (gv.y / (1.f + expf(-gv.y)));
        bf16 h0 = __float2bfloat16_rn(t0), h1 = __float2bfloat16_rn(t1);
        bf162 hp; hp.x = h0; hp.y = h1;
        th2[idx] = hp;
        bf162 lp;
        lp.x = __float2bfloat16_rn(t0 - __bfloat162float(h0));
        lp.y = __float2bfloat16_rn(t1 - __bfloat162float(h1));
        tl2[idx] = lp;
    }
}

// ---------------- launch ------------------------------------------------------
extern "C" void kernel_launch(void* const* d_in, const int* in_sizes, int n_in,
                              void* d_out, int out_size)
{
    const float* x   = (const float*)d_in[0];
    const float* Wq  = (const float*)d_in[1];
    const float* Wk  = (const float*)d_in[2];
    const float* Wog = (const float*)d_in[3];
    const float* Wig = (const float*)d_in[4];
    const float* Wo  = (const float*)d_in[5];
    const float* gw  = (const float*)d_in[6];
    float* out = (float*)d_out;

    float *sq, *sk, *o_, *G;
    cudaGetSymbolAddress((void**)&sq, g_sq);
    cudaGetSymbolAddress((void**)&sk, g_sk);
    cudaGetSymbolAddress((void**)&o_, g_o);
    cudaGetSymbolAddress((void**)&G,  g_G);
    bf16 *xh, *xl, *wqh, *wql, *wkh, *wkl, *wogh, *wogl, *wigh, *wigl, *woh, *wol;
    bf16 *oh, *ol, *th, *tl;
    cudaGetSymbolAddress((void**)&xh, g_xh);   cudaGetSymbolAddress((void**)&xl, g_xl);
    cudaGetSymbolAddress((void**)&wqh, g_wqh); cudaGetSymbolAddress((void**)&wql, g_wql);
    cudaGetSymbolAddress((void**)&wkh, g_wkh); cudaGetSymbolAddress((void**)&wkl, g_wkl);
    cudaGetSymbolAddress((void**)&wogh, g_wogh); cudaGetSymbolAddress((void**)&wogl, g_wogl);
    cudaGetSymbolAddress((void**)&wigh, g_wigh); cudaGetSymbolAddress((void**)&wigl, g_wigl);
    cudaGetSymbolAddress((void**)&woh, g_woh); cudaGetSymbolAddress((void**)&wol, g_wol);
    cudaGetSymbolAddress((void**)&oh, g_oh);   cudaGetSymbolAddress((void**)&ol, g_ol);
    cudaGetSymbolAddress((void**)&th, g_th);   cudaGetSymbolAddress((void**)&tl, g_tl);

    cudaFuncSetAttribute(tm_gemm, cudaFuncAttributeMaxDynamicSharedMemorySize, GSMEM);

    // 0-4. hi/lo splits (5 launches so that launch #5 = tm_gemm for ncu -s 5)
    const int XN4 = NTOK * HID / 4, WN4 = HID * HID / 4, PN4 = DK * HID / 4;
    cvt_split<<<XN4 / 256, 256>>>((const float4*)x, (bf162*)xh, (bf162*)xl, XN4);
    cvt_split<<<PN4 / 256, 256>>>((const float4*)Wq, (bf162*)wqh, (bf162*)wql, PN4);
    cvt_split<<<PN4 / 256, 256>>>((const float4*)Wk, (bf162*)wkh, (bf162*)wkl, PN4);
    cvt_split<<<WN4 / 256, 256>>>((const float4*)Wog, (bf162*)wogh, (bf162*)wogl, WN4);
    cvt_split2<<<dim3(WN4 / 256, 2), 256>>>(
        (const float4*)Wig, (bf162*)wigh, (bf162*)wigl,
        (const float4*)Wo,  (bf162*)woh,  (bf162*)wol, WN4);

    // 5. q,k projections fused (z selects Wq->sq vs Wk->sk), bf16x3 phases
    tm_gemm<<<dim3(1, NTOK / 128, 2), 256, GSMEM>>>(
        xh, xl, xh, xh, xl, xh,
        wqh, wqh, wql, wkh, wkh, wkl,
        sq, sk, 3, 1, HID, DK);
    // 6. softmax / sigmoid
    qk_act<<<NTOK, DK>>>(sq, sk);
    // 7. per-chunk decay factors
    chunk_prep<<<NCC, DK>>>(sq, sk);
    // 8. intra-chunk matrices
    a_gemm<<<NCC, 256>>>();
    // 9. per-chunk state contributions T_c
    t_gemm<<<dim3(HID / 64, NCC), 256>>>(x);
    // 10. recurrent scan (in-place: T -> S_before)
    scan_k<<<512, 256>>>();
    // 11. o = A@v + qb@S_before (+ bf16 hi/lo epilogue)
    o_gemm<<<dim3(HID / 64, NCC), 256>>>(x);
    // 12. gates: G = o@Wog^T + x@Wig^T as 6 bf16 phases
    tm_gemm<<<dim3(HID / 128, NTOK / 128, 1), 256, GSMEM>>>(
        oh, ol, oh, xh, xl, xh,
        wogh, wogh, wogl, wigh, wigh, wigl,
        G, G, 6, 0, HID, HID);
    // 13. rmsnorm + silu gating -> t hi/lo
    gate_norm<<<NTOK, 256>>>(o_, G, gw, th, tl);
    // 14. final projection: out = t @ Wo^T, bf16x3
    tm_gemm<<<dim3(HID / 128, NTOK / 128, 1), 256, GSMEM>>>(
        th, tl, th, th, tl, th,
        woh, woh, wol, woh, woh, wol,
        out, out, 3, 0, HID, HID);
}